// round 4
// baseline (speedup 1.0000x reference)
#include <cuda_runtime.h>
#include <cstddef>

// GazeLSTM on GB300 (sm_103a). B=16384, T=128, half=64.
// One block = 192 threads = 3 warp-pairs serving 64 batch rows:
//   role 0: backward chain (64 threads, matvec-T, writes sout chunks)
//   role 1: forward chain  (64 threads, matvec,  writes sout chunks)
//   role 2: LSTM           (64 threads, consumes back sout one chunk behind)
// R staged per chunk (C=4 matrices/b) via 16B cp.async.cg, double-buffered;
// one __syncthreads per chunk pipelines producer->consumer.

#define BT  64
#define C   4
#define NQ  9     // float4 per b per chunk (4*9 floats = 9 quads)
#define NTH 192

__device__ __forceinline__ unsigned long long pk2(float lo, float hi) {
    unsigned long long r; asm("mov.b64 %0, {%1, %2};" : "=l"(r) : "f"(lo), "f"(hi)); return r;
}
__device__ __forceinline__ void upk2(float& lo, float& hi, unsigned long long v) {
    asm("mov.b64 {%0, %1}, %2;" : "=f"(lo), "=f"(hi) : "l"(v));
}
__device__ __forceinline__ unsigned long long fma2(unsigned long long a, unsigned long long b, unsigned long long c) {
    unsigned long long d; asm("fma.rn.f32x2 %0, %1, %2, %3;" : "=l"(d) : "l"(a), "l"(b), "l"(c)); return d;
}
__device__ __forceinline__ float tanhx(float x) {
    float y; asm("tanh.approx.f32 %0, %1;" : "=f"(y) : "f"(x)); return y;
}

#define CP16(dst_u32, src_ptr) \
    asm volatile("cp.async.cg.shared.global [%0], [%1], 16;" :: "r"(dst_u32), "l"(src_ptr))
#define CP_COMMIT() asm volatile("cp.async.commit_group;")
#define CP_WAIT1()  asm volatile("cp.async.wait_group 1;")
#define CP_WAIT0()  asm volatile("cp.async.wait_group 0;")

// Weights prescaled: sigmoid gates by 0.5 (sig(x)=0.5+0.5*tanh(x/2)), tanh gates by 1.
#define LSTM_STEP(x0, x1, x2)                                                        \
    do {                                                                             \
        unsigned long long xx0 = pk2((x0), (x0)), xx1 = pk2((x1), (x1)), xx2 = pk2((x2), (x2)); \
        unsigned long long hh0 = pk2(h0, h0), hh1 = pk2(h1, h1), hh2 = pk2(h2, h2);  \
        float th[12];                                                                \
        _Pragma("unroll") for (int p = 0; p < 6; p++) {                              \
            unsigned long long g =                                                   \
                fma2(WI[p][0], xx0, fma2(WI[p][1], xx1, fma2(WI[p][2], xx2,          \
                fma2(WH[p][0], hh0, fma2(WH[p][1], hh1, fma2(WH[p][2], hh2, BS[p])))))); \
            float a_, b_; upk2(a_, b_, g);                                           \
            th[2 * p] = tanhx(a_); th[2 * p + 1] = tanhx(b_);                        \
        }                                                                            \
        float i0 = fmaf(0.5f, th[0], 0.5f), i1 = fmaf(0.5f, th[1], 0.5f), i2 = fmaf(0.5f, th[2], 0.5f); \
        float f0 = fmaf(0.5f, th[3], 0.5f), f1 = fmaf(0.5f, th[4], 0.5f), f2 = fmaf(0.5f, th[5], 0.5f); \
        float o0 = fmaf(0.5f, th[9], 0.5f), o1 = fmaf(0.5f, th[10], 0.5f), o2 = fmaf(0.5f, th[11], 0.5f); \
        c0 = fmaf(f0, c0, i0 * th[6]);                                               \
        c1 = fmaf(f1, c1, i1 * th[7]);                                               \
        c2 = fmaf(f2, c2, i2 * th[8]);                                               \
        h0 = o0 * tanhx(c0); h1 = o1 * tanhx(c1); h2 = o2 * tanhx(c2);               \
    } while (0)

// Stage one chunk: 64 b's x NQ quads, coalesced 16B cp.async. j0 % 4 == 0 required.
__device__ __forceinline__ void stage_chunk(float4* __restrict__ sdst,
                                            const float4* __restrict__ src4base,
                                            int t9q, int ltid) {
    int bp = ltid / NQ;
    int q  = ltid - bp * NQ;
#pragma unroll
    for (int k = 0; k < NQ; k++) {
        const float4* src = src4base + (size_t)bp * t9q + q;
        unsigned dst = (unsigned)__cvta_generic_to_shared(sdst + q * BT + (bp ^ q));
        CP16(dst, src);
        q += 1; bp += 7;                   // advance by 64 = 7*9 + 1
        if (q >= NQ) { q -= NQ; bp += 1; }
    }
}

// Load matrix M (0..3) of the chunk for this thread's b.
template <int M>
__device__ __forceinline__ void loadA(float* A, const float4* __restrict__ buf, int ltid) {
    constexpr int F0  = 9 * M;
    constexpr int QA  = F0 >> 2;
    constexpr int OFF = F0 & 3;
    float tmp[12];
    *(float4*)(tmp + 0) = buf[(QA + 0) * BT + (ltid ^ (QA + 0))];
    *(float4*)(tmp + 4) = buf[(QA + 1) * BT + (ltid ^ (QA + 1))];
    *(float4*)(tmp + 8) = buf[(QA + 2) * BT + (ltid ^ (QA + 2))];
#pragma unroll
    for (int i = 0; i < 9; i++) A[i] = tmp[OFF + i];
}

// Coalesced writeback: NF floats per b for 64 b's from swizzled sout.
template <int NF>
__device__ __forceinline__ void store_chunk(float* __restrict__ gdst, size_t T3,
                                            const float* __restrict__ sout, int ltid) {
    int bp = ltid / NF;
    int e  = ltid - bp * NF;
    constexpr int DB = BT / NF;
    constexpr int DE = BT % NF;
#pragma unroll
    for (int k = 0; k < NF; k++) {
        gdst[(size_t)bp * T3 + e] = sout[e * BT + (bp ^ e)];
        bp += DB; e += DE;
        if (e >= NF) { e -= NF; bp += 1; }
    }
}

__global__ __launch_bounds__(NTH, 2) void gaze_lstm_kernel(
    const float* __restrict__ dir,   // [B,3]
    const float* __restrict__ R,     // [B,T,3,3]
    const float* __restrict__ Wih,   // [12,3]
    const float* __restrict__ Whh,   // [12,3]
    const float* __restrict__ bih,   // [12]
    const float* __restrict__ bhh,   // [12]
    float* __restrict__ out,         // [B,T,3]
    int B, int T)
{
    __shared__ float4 sbB[2][NQ * BT];      // 2 x 9216 B
    __shared__ float4 sbF[2][NQ * BT];      // 2 x 9216 B
    __shared__ float  soB[2][3 * C * BT];   // 2 x 3072 B
    __shared__ float  soF[2][3 * C * BT];   // 2 x 3072 B  (total = 48 KB)

    const int half = T >> 1;
    const int t9q = (T * 9) >> 2;
    const size_t T3 = (size_t)T * 3;
    const int tid = threadIdx.x;
    const int w = tid >> 5;
    const int pair = w >> 1;                 // 0:(S0,S1) 1:(S2,S3) 2:(S0,S1)
    const int ltid = ((w & 1) << 5) | (tid & 31);

    // roles: pair2 = forward; LSTM alternates between pair1 (even blocks) and
    // pair0 (odd blocks) to spread MUFU across SMSPs.
    int role;
    if (pair == 2) role = 1;
    else if ((blockIdx.x & 1) == 0) role = (pair == 0) ? 0 : 2;
    else role = (pair == 0) ? 2 : 0;

    const int bbase = blockIdx.x * BT;
    const int b = bbase + ltid;
    const int nchunks = half / C;            // 16

    const float d0 = __ldg(dir + (size_t)b * 3 + 0);
    const float d1 = __ldg(dir + (size_t)b * 3 + 1);
    const float d2 = __ldg(dir + (size_t)b * 3 + 2);
    float v0 = d0, v1 = d1, v2 = d2;

    const float4* R4 = (const float4*)R + (size_t)bbase * t9q;
    float* oblk = out + (size_t)bbase * T3;

    // LSTM state + prescaled packed weights (live only on role-2 path)
    unsigned long long WI[6][3], WH[6][3], BS[6];
    float h0 = 0.f, h1 = 0.f, h2 = 0.f, c0 = 0.f, c1 = 0.f, c2 = 0.f;
    if (role == 2) {
#pragma unroll
        for (int p = 0; p < 6; p++) {
            const int g0 = 2 * p, g1 = 2 * p + 1;
            const float s0 = (g0 >= 6 && g0 <= 8) ? 1.0f : 0.5f;
            const float s1 = (g1 >= 6 && g1 <= 8) ? 1.0f : 0.5f;
#pragma unroll
            for (int j = 0; j < 3; j++) {
                WI[p][j] = pk2(__ldg(Wih + g0 * 3 + j) * s0, __ldg(Wih + g1 * 3 + j) * s1);
                WH[p][j] = pk2(__ldg(Whh + g0 * 3 + j) * s0, __ldg(Whh + g1 * 3 + j) * s1);
            }
            BS[p] = pk2((__ldg(bih + g0) + __ldg(bhh + g0)) * s0,
                        (__ldg(bih + g1) + __ldg(bhh + g1)) * s1);
        }
    }

    // prologue staging of chunk 0
    if (role == 0) { stage_chunk(sbB[0], R4 + (((half - C) * 9) >> 2), t9q, ltid); CP_COMMIT(); }
    else if (role == 1) { stage_chunk(sbF[0], R4 + ((half * 9) >> 2), t9q, ltid); CP_COMMIT(); }

    for (int cc = 0; cc <= nchunks; cc++) {
        if (cc < nchunks) {
            if (role == 0) {
                if (cc + 1 < nchunks) {
                    stage_chunk(sbB[(cc + 1) & 1], R4 + (((half - C * (cc + 2)) * 9) >> 2), t9q, ltid);
                    CP_COMMIT(); CP_WAIT1();
                } else CP_WAIT0();
            } else if (role == 1) {
                if (cc + 1 < nchunks) {
                    stage_chunk(sbF[(cc + 1) & 1], R4 + (((half + C * (cc + 1)) * 9) >> 2), t9q, ltid);
                    CP_COMMIT(); CP_WAIT1();
                } else CP_WAIT0();
            }
        }
        __syncthreads();

        if (role == 0) {
            if (cc >= 1)
                store_chunk<3 * C>(oblk + (size_t)(C * (cc - 1)) * 3, T3, soB[(cc - 1) & 1], ltid);
            if (cc < nchunks) {
                const float4* buf = sbB[cc & 1];
                float* so = soB[cc & 1];
#pragma unroll
                for (int s = 0; s < C; s++) {
                    float A[9];
                    switch (s) {   // matrix index 3-s (reverse within chunk)
                        case 0: loadA<3>(A, buf, ltid); break;
                        case 1: loadA<2>(A, buf, ltid); break;
                        case 2: loadA<1>(A, buf, ltid); break;
                        default: loadA<0>(A, buf, ltid); break;
                    }
                    float n0 = fmaf(A[6], v2, fmaf(A[3], v1, A[0] * v0));
                    float n1 = fmaf(A[7], v2, fmaf(A[4], v1, A[1] * v0));
                    float n2 = fmaf(A[8], v2, fmaf(A[5], v1, A[2] * v0));
                    v0 = n0; v1 = n1; v2 = n2;
                    const int eo = 3 * s;
                    so[(eo + 0) * BT + (ltid ^ (eo + 0))] = v0;
                    so[(eo + 1) * BT + (ltid ^ (eo + 1))] = v1;
                    so[(eo + 2) * BT + (ltid ^ (eo + 2))] = v2;
                }
            }
        } else if (role == 1) {
            if (cc >= 1) {
                const int k = cc - 1;
                float* gdst = oblk + (size_t)(half + 1 + C * k) * 3;
                if (k < nchunks - 1) store_chunk<3 * C>(gdst, T3, soF[k & 1], ltid);
                else                 store_chunk<9>(gdst, T3, soF[k & 1], ltid);  // 3 steps
            }
            if (cc < nchunks) {
                int ns = (T - 1 - half) - C * cc;           // 4 ... 4, 3
                ns = ns > C ? C : ns;
                const float4* buf = sbF[cc & 1];
                float* so = soF[cc & 1];
#pragma unroll
                for (int s = 0; s < C; s++) {
                    if (s < ns) {
                        float A[9];
                        switch (s) {
                            case 0: loadA<0>(A, buf, ltid); break;
                            case 1: loadA<1>(A, buf, ltid); break;
                            case 2: loadA<2>(A, buf, ltid); break;
                            default: loadA<3>(A, buf, ltid); break;
                        }
                        float n0 = fmaf(A[2], v2, fmaf(A[1], v1, A[0] * v0));
                        float n1 = fmaf(A[5], v2, fmaf(A[4], v1, A[3] * v0));
                        float n2 = fmaf(A[8], v2, fmaf(A[7], v1, A[6] * v0));
                        v0 = n0; v1 = n1; v2 = n2;
                        const int eo = 3 * s;
                        so[(eo + 0) * BT + (ltid ^ (eo + 0))] = v0;
                        so[(eo + 1) * BT + (ltid ^ (eo + 1))] = v1;
                        so[(eo + 2) * BT + (ltid ^ (eo + 2))] = v2;
                    }
                }
            }
        } else {
            if (cc >= 1) {
                const float* so = soB[(cc - 1) & 1];
#pragma unroll
                for (int s = 0; s < C; s++) {
                    const int e = 3 * s;
                    float x0 = so[(e + 0) * BT + (ltid ^ (e + 0))];
                    float x1 = so[(e + 1) * BT + (ltid ^ (e + 1))];
                    float x2 = so[(e + 2) * BT + (ltid ^ (e + 2))];
                    LSTM_STEP(x0, x1, x2);
                }
            }
        }
    }

    if (role == 2) {
        // final step consumes dir; h is the output row at t = half
        LSTM_STEP(d0, d1, d2);
        float* ob = oblk + (size_t)ltid * T3 + (size_t)half * 3;
        ob[0] = h0; ob[1] = h1; ob[2] = h2;
    }
}

extern "C" void kernel_launch(void* const* d_in, const int* in_sizes, int n_in,
                              void* d_out, int out_size)
{
    const float* dir = (const float*)d_in[0];
    const float* R   = (const float*)d_in[1];
    const float* Wih = (const float*)d_in[2];
    const float* Whh = (const float*)d_in[3];
    const float* bih = (const float*)d_in[4];
    const float* bhh = (const float*)d_in[5];
    float* out = (float*)d_out;

    const int B = in_sizes[0] / 3;
    const int T = in_sizes[1] / (B * 9);

    gaze_lstm_kernel<<<B / BT, NTH>>>(dir, R, Wih, Whh, bih, bhh, out, B, T);
}